// round 3
// baseline (speedup 1.0000x reference)
#include <cuda_runtime.h>
#include <cuda_bf16.h>

#define N_NODES 50000
#define N_EDGES 800000
#define DIM 64

// Scratch (device globals — no allocation allowed). BSS zero-init at load;
// g_deg is re-zeroed inside k_scan every run so k_hist can assume 0 on entry.
__device__ int   g_deg[N_NODES];
__device__ int   g_row[N_NODES + 1];
__device__ int   g_cur[N_NODES];
__device__ int   g_col[N_EDGES];
__device__ float g_x1[N_NODES * DIM];
__device__ float g_agg[N_NODES * DIM];

// ------------------------------------------------------------------ hist
__global__ void k_hist(const int* __restrict__ ei) {
    int e = blockIdx.x * blockDim.x + threadIdx.x;
    if (e < N_EDGES) atomicAdd(&g_deg[ei[N_EDGES + e]], 1);
}

// ------------------------------------------------- one-block exclusive scan
// Scans g_deg -> g_row/g_cur, zeroes g_deg for the next replay, writes sentinel.
__global__ void __launch_bounds__(1024) k_scan() {
    __shared__ int wsum[32];
    int t = threadIdx.x, lane = t & 31, wid = t >> 5;
    int base = 0;
    const int NCHUNK = (N_NODES + 1023) / 1024;
    for (int chunk = 0; chunk < NCHUNK; chunk++) {
        int i = chunk * 1024 + t;
        int v = 0;
        if (i < N_NODES) { v = g_deg[i]; g_deg[i] = 0; }
        // inclusive warp scan
        int sc = v;
        #pragma unroll
        for (int off = 1; off < 32; off <<= 1) {
            int n = __shfl_up_sync(0xffffffffu, sc, off);
            if (lane >= off) sc += n;
        }
        if (lane == 31) wsum[wid] = sc;
        __syncthreads();
        if (wid == 0) {
            int w = wsum[lane];
            #pragma unroll
            for (int off = 1; off < 32; off <<= 1) {
                int n = __shfl_up_sync(0xffffffffu, w, off);
                if (lane >= off) w += n;
            }
            wsum[lane] = w;
        }
        __syncthreads();
        int wpre = (wid > 0) ? wsum[wid - 1] : 0;
        int ex = base + wpre + sc - v;     // exclusive prefix
        if (i < N_NODES) { g_row[i] = ex; g_cur[i] = ex; }
        int total = wsum[31];
        __syncthreads();                   // protect wsum before next chunk
        base += total;
    }
    if (t == 0) g_row[N_NODES] = N_EDGES;
}

// --------------------------------------------------------------- scatter
__global__ void k_scatter(const int* __restrict__ ei) {
    int e = blockIdx.x * blockDim.x + threadIdx.x;
    if (e < N_EDGES) {
        int d = ei[N_EDGES + e];
        int p = atomicAdd(&g_cur[d], 1);
        g_col[p] = ei[e];
    }
}

// ------------------------------------------------------------- aggregation
// One warp per node: mean over {self} ∪ in-neighbors -> g_agg.
__global__ void k_agg(const float* __restrict__ x) {
    int w    = (blockIdx.x * blockDim.x + threadIdx.x) >> 5;
    int lane = threadIdx.x & 31;
    if (w >= N_NODES) return;

    const float2* xs = (const float2*)x;
    float2 v = xs[w * 32 + lane];
    float a0 = v.x, a1 = v.y;

    int start = g_row[w];
    int cnt   = g_row[w + 1] - start;

    for (int base = 0; base < cnt; base += 32) {
        int rem = cnt - base;
        int m   = rem < 32 ? rem : 32;
        int c   = (lane < m) ? g_col[start + base + lane] : 0;
        int t = 0;
        for (; t + 4 <= m; t += 4) {
            int s0 = __shfl_sync(0xffffffffu, c, t);
            int s1 = __shfl_sync(0xffffffffu, c, t + 1);
            int s2 = __shfl_sync(0xffffffffu, c, t + 2);
            int s3 = __shfl_sync(0xffffffffu, c, t + 3);
            float2 v0 = xs[s0 * 32 + lane];
            float2 v1 = xs[s1 * 32 + lane];
            float2 v2 = xs[s2 * 32 + lane];
            float2 v3 = xs[s3 * 32 + lane];
            a0 += v0.x; a1 += v0.y;
            a0 += v1.x; a1 += v1.y;
            a0 += v2.x; a1 += v2.y;
            a0 += v3.x; a1 += v3.y;
        }
        for (; t < m; t++) {
            int s = __shfl_sync(0xffffffffu, c, t);
            float2 vv = xs[s * 32 + lane];
            a0 += vv.x; a1 += vv.y;
        }
    }
    float inv = 1.0f / (float)(cnt + 1);
    ((float2*)g_agg)[w * 32 + lane] = make_float2(a0 * inv, a1 * inv);
}

// ------------------------------------------------------------------- GEMM
// out[n] = relu( agg[n] @ Wl + bl + x[n] @ Wr )
// 256 threads / 128 nodes per block. Everything staged in 96KB dynamic smem
// up front (1 barrier), then a pure FFMA loop (no global latency exposure).
__global__ void __launch_bounds__(256) k_mm(const float* __restrict__ x,
                                            const float* __restrict__ Wl,
                                            const float* __restrict__ bl,
                                            const float* __restrict__ Wr,
                                            float* __restrict__ out) {
    extern __shared__ float sm[];
    float* wl_s = sm;                 // [64][64]
    float* wr_s = sm + 4096;          // [64][64]
    float* a_s  = sm + 8192;          // [64 k][128 node]
    float* x_s  = sm + 16384;         // [64 k][128 node]

    int tid   = threadIdx.x;
    int node0 = blockIdx.x * 128;

    // stage weights (16 float4 per thread)
    for (int i = tid; i < DIM * DIM / 4; i += 256) {
        ((float4*)wl_s)[i] = ((const float4*)Wl)[i];
        ((float4*)wr_s)[i] = ((const float4*)Wr)[i];
    }
    // stage inputs k-major: thread covers node nl, k half kh..kh+31
    {
        int nl = tid & 127;
        int kh = (tid >> 7) * 32;
        int node = node0 + nl;
        bool ok = node < N_NODES;
        const float4* xr = (const float4*)(x     + node * DIM + kh);
        const float4* ar = (const float4*)(g_agg + node * DIM + kh);
        #pragma unroll
        for (int j = 0; j < 8; j++) {
            float4 vx = ok ? xr[j] : make_float4(0.f, 0.f, 0.f, 0.f);
            float4 va = ok ? ar[j] : make_float4(0.f, 0.f, 0.f, 0.f);
            int k = kh + j * 4;
            x_s[(k + 0) * 128 + nl] = vx.x;
            x_s[(k + 1) * 128 + nl] = vx.y;
            x_s[(k + 2) * 128 + nl] = vx.z;
            x_s[(k + 3) * 128 + nl] = vx.w;
            a_s[(k + 0) * 128 + nl] = va.x;
            a_s[(k + 1) * 128 + nl] = va.y;
            a_s[(k + 2) * 128 + nl] = va.z;
            a_s[(k + 3) * 128 + nl] = va.w;
        }
    }
    __syncthreads();

    int nrow = (tid >> 3) << 2;   // 0,4,...,124
    int fcol = (tid & 7) << 3;    // 0,8,...,56

    float acc[4][8];
    #pragma unroll
    for (int i = 0; i < 4; i++)
        #pragma unroll
        for (int f = 0; f < 8; f++) acc[i][f] = 0.f;

    #pragma unroll 8
    for (int kk = 0; kk < DIM; kk++) {
        float wlv[8], wrv[8];
        *(float4*)&wlv[0] = *(const float4*)&wl_s[kk * DIM + fcol];
        *(float4*)&wlv[4] = *(const float4*)&wl_s[kk * DIM + fcol + 4];
        *(float4*)&wrv[0] = *(const float4*)&wr_s[kk * DIM + fcol];
        *(float4*)&wrv[4] = *(const float4*)&wr_s[kk * DIM + fcol + 4];
        #pragma unroll
        for (int i = 0; i < 4; i++) {
            float av = a_s[kk * 128 + nrow + i];
            float xv = x_s[kk * 128 + nrow + i];
            #pragma unroll
            for (int f = 0; f < 8; f++)
                acc[i][f] += av * wlv[f] + xv * wrv[f];
        }
    }

    float bv[8];
    *(float4*)&bv[0] = *(const float4*)(bl + fcol);
    *(float4*)&bv[4] = *(const float4*)(bl + fcol + 4);

    #pragma unroll
    for (int i = 0; i < 4; i++) {
        int node = node0 + nrow + i;
        if (node < N_NODES) {
            float4 o0, o1;
            o0.x = fmaxf(acc[i][0] + bv[0], 0.f);
            o0.y = fmaxf(acc[i][1] + bv[1], 0.f);
            o0.z = fmaxf(acc[i][2] + bv[2], 0.f);
            o0.w = fmaxf(acc[i][3] + bv[3], 0.f);
            o1.x = fmaxf(acc[i][4] + bv[4], 0.f);
            o1.y = fmaxf(acc[i][5] + bv[5], 0.f);
            o1.z = fmaxf(acc[i][6] + bv[6], 0.f);
            o1.w = fmaxf(acc[i][7] + bv[7], 0.f);
            *(float4*)(out + node * DIM + fcol)     = o0;
            *(float4*)(out + node * DIM + fcol + 4) = o1;
        }
    }
}

// ------------------------------------------------------------------ launch
extern "C" void kernel_launch(void* const* d_in, const int* in_sizes, int n_in,
                              void* d_out, int out_size) {
    const float* x   = (const float*)d_in[0];
    const int*   ei  = (const int*)  d_in[1];
    const float* Wl0 = (const float*)d_in[2];
    const float* bl0 = (const float*)d_in[3];
    const float* Wr0 = (const float*)d_in[4];
    const float* Wl1 = (const float*)d_in[5];
    const float* bl1 = (const float*)d_in[6];
    const float* Wr1 = (const float*)d_in[7];
    float* out = (float*)d_out;

    const int MM_SMEM = 24576 * sizeof(float);   // 96 KB dynamic
    cudaFuncSetAttribute(k_mm, cudaFuncAttributeMaxDynamicSharedMemorySize, MM_SMEM);

    int agg_blocks = (N_NODES * 32 + 255) / 256;
    int mm_blocks  = (N_NODES + 127) / 128;

    k_hist   <<<(N_EDGES + 255) / 256, 256>>>(ei);   // launch 0
    k_scan   <<<1, 1024>>>();                         // launch 1
    k_scatter<<<(N_EDGES + 255) / 256, 256>>>(ei);   // launch 2
    k_agg    <<<agg_blocks, 256>>>(x);                // launch 3  <- ncu capture target
    k_mm     <<<mm_blocks, 256, MM_SMEM>>>(x, Wl0, bl0, Wr0, g_x1);
    k_agg    <<<agg_blocks, 256>>>(g_x1);
    k_mm     <<<mm_blocks, 256, MM_SMEM>>>(g_x1, Wl1, bl1, Wr1, out);
}

// round 4
// speedup vs baseline: 1.0321x; 1.0321x over previous
#include <cuda_runtime.h>
#include <cuda_bf16.h>

#define N_NODES 50000
#define N_EDGES 800000
#define DIM 64
#define NB_SCAN 49   // ceil(50000/1024)

// Scratch (device globals — no allocation allowed). BSS zero-init at load;
// g_deg is re-zeroed inside k_scan1 every run so k_hist can assume 0 on entry.
__device__ int   g_deg[N_NODES];
__device__ int   g_row[N_NODES + 1];
__device__ int   g_cur[N_NODES];
__device__ int   g_col[N_EDGES];
__device__ int   g_bsum[64];
__device__ float g_x1[N_NODES * DIM];
__device__ float g_agg[N_NODES * DIM];

// ------------------------------------------------------------------ hist
__global__ void k_hist(const int* __restrict__ ei) {
    int e = blockIdx.x * blockDim.x + threadIdx.x;
    if (e < N_EDGES) atomicAdd(&g_deg[e < N_EDGES ? ei[N_EDGES + e] : 0], 1);
}

// ---------------------------------------------- per-block exclusive scan
// Writes block-local exclusive prefix to g_row, block totals to g_bsum,
// zeroes g_deg (ready for next replay's k_hist).
__global__ void __launch_bounds__(1024) k_scan1() {
    __shared__ int wsum[32];
    int t = threadIdx.x, lane = t & 31, wid = t >> 5;
    int i = blockIdx.x * 1024 + t;
    int v = 0;
    if (i < N_NODES) { v = g_deg[i]; g_deg[i] = 0; }
    int sc = v;
    #pragma unroll
    for (int off = 1; off < 32; off <<= 1) {
        int n = __shfl_up_sync(0xffffffffu, sc, off);
        if (lane >= off) sc += n;
    }
    if (lane == 31) wsum[wid] = sc;
    __syncthreads();
    if (wid == 0) {
        int w = wsum[lane];
        #pragma unroll
        for (int off = 1; off < 32; off <<= 1) {
            int n = __shfl_up_sync(0xffffffffu, w, off);
            if (lane >= off) w += n;
        }
        wsum[lane] = w;
    }
    __syncthreads();
    int wpre = (wid > 0) ? wsum[wid - 1] : 0;
    if (i < N_NODES) g_row[i] = wpre + sc - v;
    if (t == 0) g_bsum[blockIdx.x] = wsum[31];
}

// ------------------------------- add cross-block offsets, write g_cur
__global__ void __launch_bounds__(1024) k_scan23() {
    __shared__ int s_off;
    int t = threadIdx.x, lane = t & 31, wid = t >> 5;
    if (wid == 0) {
        int b = blockIdx.x;
        int v = (lane < b) ? g_bsum[lane] : 0;
        if (lane + 32 < b) v += g_bsum[lane + 32];
        #pragma unroll
        for (int off = 16; off > 0; off >>= 1)
            v += __shfl_down_sync(0xffffffffu, v, off);
        if (lane == 0) s_off = v;
    }
    __syncthreads();
    int off = s_off;
    int i = blockIdx.x * 1024 + t;
    if (i < N_NODES) {
        int r = g_row[i] + off;
        g_row[i] = r;
        g_cur[i] = r;
    }
    if (i == 0) g_row[N_NODES] = N_EDGES;
}

// --------------------------------------------------------------- scatter
__global__ void k_scatter(const int* __restrict__ ei) {
    int e = blockIdx.x * blockDim.x + threadIdx.x;
    if (e < N_EDGES) {
        int d = ei[N_EDGES + e];
        int p = atomicAdd(&g_cur[d], 1);
        g_col[p] = ei[e];
    }
}

// ------------------------------------------------------------- aggregation
// One warp per node: mean over {self} ∪ in-neighbors -> g_agg.
__global__ void k_agg(const float* __restrict__ x) {
    int w    = (blockIdx.x * blockDim.x + threadIdx.x) >> 5;
    int lane = threadIdx.x & 31;
    if (w >= N_NODES) return;

    const float2* xs = (const float2*)x;
    float2 v = xs[w * 32 + lane];
    float a0 = v.x, a1 = v.y;

    int start = g_row[w];
    int cnt   = g_row[w + 1] - start;

    for (int base = 0; base < cnt; base += 32) {
        int rem = cnt - base;
        int m   = rem < 32 ? rem : 32;
        int c   = (lane < m) ? g_col[start + base + lane] : 0;
        int t = 0;
        for (; t + 4 <= m; t += 4) {
            int s0 = __shfl_sync(0xffffffffu, c, t);
            int s1 = __shfl_sync(0xffffffffu, c, t + 1);
            int s2 = __shfl_sync(0xffffffffu, c, t + 2);
            int s3 = __shfl_sync(0xffffffffu, c, t + 3);
            float2 v0 = xs[s0 * 32 + lane];
            float2 v1 = xs[s1 * 32 + lane];
            float2 v2 = xs[s2 * 32 + lane];
            float2 v3 = xs[s3 * 32 + lane];
            a0 += v0.x; a1 += v0.y;
            a0 += v1.x; a1 += v1.y;
            a0 += v2.x; a1 += v2.y;
            a0 += v3.x; a1 += v3.y;
        }
        for (; t < m; t++) {
            int s = __shfl_sync(0xffffffffu, c, t);
            float2 vv = xs[s * 32 + lane];
            a0 += vv.x; a1 += vv.y;
        }
    }
    float inv = 1.0f / (float)(cnt + 1);
    ((float2*)g_agg)[w * 32 + lane] = make_float2(a0 * inv, a1 * inv);
}

// ------------------------------------------------------------------- GEMM
// out[n] = relu( agg[n] @ Wl + bl + x[n] @ Wr )
// 256 threads / 128 nodes per block, 96KB dynamic smem, single barrier.
__global__ void __launch_bounds__(256, 2) k_mm(const float* __restrict__ x,
                                               const float* __restrict__ Wl,
                                               const float* __restrict__ bl,
                                               const float* __restrict__ Wr,
                                               float* __restrict__ out) {
    extern __shared__ float sm[];
    float* wl_s = sm;                 // [64][64]
    float* wr_s = sm + 4096;          // [64][64]
    float* a_s  = sm + 8192;          // [64 k][128 node]
    float* x_s  = sm + 16384;         // [64 k][128 node]

    int tid   = threadIdx.x;
    int node0 = blockIdx.x * 128;

    for (int i = tid; i < DIM * DIM / 4; i += 256) {
        ((float4*)wl_s)[i] = ((const float4*)Wl)[i];
        ((float4*)wr_s)[i] = ((const float4*)Wr)[i];
    }
    {
        int nl = tid & 127;
        int kh = (tid >> 7) * 32;
        int node = node0 + nl;
        bool ok = node < N_NODES;
        const float4* xr = (const float4*)(x     + node * DIM + kh);
        const float4* ar = (const float4*)(g_agg + node * DIM + kh);
        #pragma unroll
        for (int j = 0; j < 8; j++) {
            float4 vx = ok ? xr[j] : make_float4(0.f, 0.f, 0.f, 0.f);
            float4 va = ok ? ar[j] : make_float4(0.f, 0.f, 0.f, 0.f);
            int k = kh + j * 4;
            x_s[(k + 0) * 128 + nl] = vx.x;
            x_s[(k + 1) * 128 + nl] = vx.y;
            x_s[(k + 2) * 128 + nl] = vx.z;
            x_s[(k + 3) * 128 + nl] = vx.w;
            a_s[(k + 0) * 128 + nl] = va.x;
            a_s[(k + 1) * 128 + nl] = va.y;
            a_s[(k + 2) * 128 + nl] = va.z;
            a_s[(k + 3) * 128 + nl] = va.w;
        }
    }
    __syncthreads();

    int nrow = (tid >> 3) << 2;   // 0,4,...,124
    int fcol = (tid & 7) << 3;    // 0,8,...,56

    float acc[4][8];
    #pragma unroll
    for (int i = 0; i < 4; i++)
        #pragma unroll
        for (int f = 0; f < 8; f++) acc[i][f] = 0.f;

    #pragma unroll 8
    for (int kk = 0; kk < DIM; kk++) {
        float wlv[8], wrv[8];
        *(float4*)&wlv[0] = *(const float4*)&wl_s[kk * DIM + fcol];
        *(float4*)&wlv[4] = *(const float4*)&wl_s[kk * DIM + fcol + 4];
        *(float4*)&wrv[0] = *(const float4*)&wr_s[kk * DIM + fcol];
        *(float4*)&wrv[4] = *(const float4*)&wr_s[kk * DIM + fcol + 4];
        #pragma unroll
        for (int i = 0; i < 4; i++) {
            float av = a_s[kk * 128 + nrow + i];
            float xv = x_s[kk * 128 + nrow + i];
            #pragma unroll
            for (int f = 0; f < 8; f++)
                acc[i][f] += av * wlv[f] + xv * wrv[f];
        }
    }

    float bv[8];
    *(float4*)&bv[0] = *(const float4*)(bl + fcol);
    *(float4*)&bv[4] = *(const float4*)(bl + fcol + 4);

    #pragma unroll
    for (int i = 0; i < 4; i++) {
        int node = node0 + nrow + i;
        if (node < N_NODES) {
            float4 o0, o1;
            o0.x = fmaxf(acc[i][0] + bv[0], 0.f);
            o0.y = fmaxf(acc[i][1] + bv[1], 0.f);
            o0.z = fmaxf(acc[i][2] + bv[2], 0.f);
            o0.w = fmaxf(acc[i][3] + bv[3], 0.f);
            o1.x = fmaxf(acc[i][4] + bv[4], 0.f);
            o1.y = fmaxf(acc[i][5] + bv[5], 0.f);
            o1.z = fmaxf(acc[i][6] + bv[6], 0.f);
            o1.w = fmaxf(acc[i][7] + bv[7], 0.f);
            *(float4*)(out + node * DIM + fcol)     = o0;
            *(float4*)(out + node * DIM + fcol + 4) = o1;
        }
    }
}

// ------------------------------------------------------------------ launch
extern "C" void kernel_launch(void* const* d_in, const int* in_sizes, int n_in,
                              void* d_out, int out_size) {
    const float* x   = (const float*)d_in[0];
    const int*   ei  = (const int*)  d_in[1];
    const float* Wl0 = (const float*)d_in[2];
    const float* bl0 = (const float*)d_in[3];
    const float* Wr0 = (const float*)d_in[4];
    const float* Wl1 = (const float*)d_in[5];
    const float* bl1 = (const float*)d_in[6];
    const float* Wr1 = (const float*)d_in[7];
    float* out = (float*)d_out;

    const int MM_SMEM = 24576 * sizeof(float);   // 96 KB dynamic
    cudaFuncSetAttribute(k_mm, cudaFuncAttributeMaxDynamicSharedMemorySize, MM_SMEM);

    int agg_blocks = (N_NODES * 32 + 255) / 256;
    int mm_blocks  = (N_NODES + 127) / 128;

    k_hist   <<<(N_EDGES + 255) / 256, 256>>>(ei);     // launch 1
    k_scan1  <<<NB_SCAN, 1024>>>();                    // launch 2
    k_scan23 <<<NB_SCAN, 1024>>>();                    // launch 3
    k_scatter<<<(N_EDGES + 255) / 256, 256>>>(ei);     // launch 4
    k_agg    <<<agg_blocks, 256>>>(x);                 // launch 5
    k_mm     <<<mm_blocks, 256, MM_SMEM>>>(x, Wl0, bl0, Wr0, g_x1);  // launch 6 <- ncu
    k_agg    <<<agg_blocks, 256>>>(g_x1);              // launch 7
    k_mm     <<<mm_blocks, 256, MM_SMEM>>>(g_x1, Wl1, bl1, Wr1, out);// launch 8
}